// round 12
// baseline (speedup 1.0000x reference)
#include <cuda_runtime.h>
#include <cstdint>

#define NMAX   500000
#define HBITS  21
#define HSIZE  (1u << HBITS)
#define HMASK  (HSIZE - 1u)
#define EMPTYK 0xFFFFFFFFu
#define SP     40          // act smem point-stride (floats)
#define MSP    72          // ms smem channel-stride (floats): [pt][chan] padded

typedef unsigned long long ull;
typedef unsigned int uint;

// ---------------- device scratch ----------------
__device__ uint32_t g_keys[3][HSIZE];
__device__ int      g_vals[3][HSIZE];
__device__ int      g_counter[3];
__device__ int      g_pt2vox[3][NMAX];
__device__ float    g_sums[3][NMAX * 64];
__device__ int      g_counts[3][NMAX];
__device__ float    g_inv[3][NMAX];
__device__ int      g_ptidx[3][NMAX];

__device__ __forceinline__ uint32_t hash32(uint32_t x) {
    x ^= x >> 16; x *= 0x85ebca6bu;
    x ^= x >> 13; x *= 0xc2b2ae35u;
    x ^= x >> 16;
    return x;
}

__device__ __forceinline__ uint f2tf(float v) {
    uint r;
    asm("cvt.rna.tf32.f32 %0, %1;" : "=r"(r) : "f"(v));
    return r;
}

// D += A(tf32) * B(tf32), m16n8k8, A row-major, B col-major, fp32 accum
__device__ __forceinline__ void mma_tf32(float4& d, const uint* a, uint b0, uint b1) {
    asm("mma.sync.aligned.m16n8k8.row.col.f32.tf32.tf32.f32 "
        "{%0,%1,%2,%3}, {%4,%5,%6,%7}, {%8,%9}, {%0,%1,%2,%3};"
        : "+f"(d.x), "+f"(d.y), "+f"(d.z), "+f"(d.w)
        : "r"(a[0]), "r"(a[1]), "r"(a[2]), "r"(a[3]), "r"(b0), "r"(b1));
}

// ---------------- K1: clear hash tables + counts ----------------
__global__ void k_clear(int n) {
    int tid = blockIdx.x * blockDim.x + threadIdx.x;
    int stride = gridDim.x * blockDim.x;
    for (int i = tid; i < (int)HSIZE; i += stride) {
        g_keys[0][i] = EMPTYK; g_keys[1][i] = EMPTYK; g_keys[2][i] = EMPTYK;
        g_vals[0][i] = -1;     g_vals[1][i] = -1;     g_vals[2][i] = -1;
    }
    for (int i = tid; i < n; i += stride) {
        g_counts[0][i] = 0; g_counts[1][i] = 0; g_counts[2][i] = 0;
    }
    if (tid == 0) { g_counter[0] = 0; g_counter[1] = 0; g_counter[2] = 0; }
}

// ---------------- K2: hash-insert (all scales via blockIdx.y) ----------------
__global__ void k_insert(const int* __restrict__ coords, int n) {
    int i = blockIdx.x * blockDim.x + threadIdx.x;
    if (i >= n) return;
    int si = blockIdx.y;
    int shift = si + 1;
    int4 cd = reinterpret_cast<const int4*>(coords)[i];
    int vx = cd.x >> shift, vy = cd.y >> shift, vz = cd.z >> shift;
    uint32_t key = (uint32_t)((((cd.w * 512) + vx) * 512 + vy) * 512 + vz);
    uint32_t slot = hash32(key) & HMASK;
    int id = -1;
#pragma unroll 1
    while (true) {
        uint32_t old = atomicCAS(&g_keys[si][slot], EMPTYK, key);
        if (old == EMPTYK) {
            id = atomicAdd(&g_counter[si], 1);
            atomicExch(&g_vals[si][slot], id);
            break;
        }
        if (old == key) {
            volatile int* vp = (volatile int*)&g_vals[si][slot];
#pragma unroll 1
            while ((id = *vp) < 0) { __nanosleep(40); }
            break;
        }
        slot = (slot + 1) & HMASK;
    }
    g_pt2vox[si][i] = id;
    atomicAdd(&g_counts[si][id], 1);
}

// ---------------- K2b: zero live prefix of sums + per-voxel 1/count ----------------
__global__ void k_post() {
    int tid = blockIdx.x * blockDim.x + threadIdx.x;
    int stride = gridDim.x * blockDim.x;
    float4 z = make_float4(0.f, 0.f, 0.f, 0.f);
#pragma unroll
    for (int s = 0; s < 3; s++) {
        int nv = g_counter[s];
        float4* s4 = reinterpret_cast<float4*>(&g_sums[s][0]);
        int m4 = nv * 16;
        for (int i = tid; i < m4; i += stride) s4[i] = z;
        for (int i = tid; i < nv; i += stride)
            g_inv[s][i] = 1.0f / (float)g_counts[s][i];
    }
}

// ---------------- K3: per-voxel feature sums (all 3 scales, one feats read) ----------------
__global__ void k_accum(const float* __restrict__ feats, int n) {
    int tid = blockIdx.x * blockDim.x + threadIdx.x;
    if (tid >= n * 16) return;
    int p = tid >> 4, q = tid & 15;
    float4 v = reinterpret_cast<const float4*>(feats)[tid];
#pragma unroll
    for (int si = 0; si < 3; si++) {
        int vid = g_pt2vox[si][p];
        float* dst = &g_sums[si][(size_t)vid * 64 + q * 4];
        asm volatile("red.global.add.v4.f32 [%0], {%1, %2, %3, %4};"
                     :: "l"(dst), "f"(v.x), "f"(v.y), "f"(v.z), "f"(v.w)
                     : "memory");
    }
}

// ---------------- K4: 8-corner probe + exact trilinear argmax ----------------
__device__ __forceinline__ int hlookup(int si, uint32_t key) {
    uint32_t slot = hash32(key) & HMASK;
#pragma unroll 1
    while (true) {
        uint32_t k = g_keys[si][slot];
        if (k == key) return g_vals[si][slot];
        if (k == EMPTYK) return -1;
        slot = (slot + 1) & HMASK;
    }
}

__global__ void k_select(const int* __restrict__ coords, int n) {
    int i = blockIdx.x * blockDim.x + threadIdx.x;
    if (i >= n) return;
    int si = blockIdx.y;
    int shift = si + 1;
    int4 cd = reinterpret_cast<const int4*>(coords)[i];
    int scale = 1 << shift;
    float invs = 1.0f / (float)scale;
    int vx = cd.x >> shift, vy = cd.y >> shift, vz = cd.z >> shift;
    float fx = (float)(cd.x - (vx << shift)) * invs;   // exact binary fractions
    float fy = (float)(cd.y - (vy << shift)) * invs;
    float fz = (float)(cd.z - (vz << shift)) * invs;
    float gx = 1.0f - fx, gy = 1.0f - fy, gz = 1.0f - fz;

    float bestw = -1.0f;
    int bestid = 0;
#pragma unroll
    for (int j = 0; j < 8; j++) {
        int bx = (j >> 2) & 1, by = (j >> 1) & 1, bz = j & 1;
        float w = (bx ? fx : gx) * (by ? fy : gy) * (bz ? fz : gz);  // exact
        uint32_t key = (uint32_t)((((cd.w * 512) + (vx + bx)) * 512 + (vy + by)) * 512 + (vz + bz));
        int id = hlookup(si, key);
        float val = (id >= 0) ? w : 0.0f;
        if (val > bestw) { bestw = val; bestid = id; }  // first-max == jnp.argmax
    }
    g_ptidx[si][i] = bestid;
}

// ---------------- K5: fused 3-scale tf32 MLP + attention + output ----------------
// CTA = 384 thr = 3 scale-groups x 4 warps. Group g handles scale g; within a
// group, warp w owns output channels [16w,16w+16) with W1/W2 A-fragments in
// registers. All groups process the SAME 32-point tile in lockstep; per-scale
// ms lands in msT[3] ([pt][chan], stride 72); attention + blend done in-CTA.
// smem (floats): fT 2560 | resT 3*2560 | msT 3*2304 | attv 128  = 17280 (69KB)
#define OFF_RES  2560
#define OFF_MS   10240
#define OFF_ATT  17152
#define SMEM_MLP (17280 * 4)

__global__ __launch_bounds__(384, 1) void k_mlp3(
    const float* __restrict__ feats,
    const float* __restrict__ W1g, const float* __restrict__ b1g,
    const float* __restrict__ W2g, const float* __restrict__ b2g,
    const float* __restrict__ Wag, const float* __restrict__ bag,
    float* __restrict__ out, int n)
{
    extern __shared__ float sm[];
    const int tid = threadIdx.x;
    const int s   = tid >> 7;          // scale group 0..2
    const int w   = (tid >> 5) & 3;    // warp in group
    const int l   = tid & 31;
    const int gr  = l >> 2;            // 0..7
    const int tg  = l & 3;             // 0..3
    const int m0  = 16 * w + gr;

    float* fT   = sm;                  // [chan][pt] stride SP (group 0 writes)
    float* resT = sm + OFF_RES + s * 2560;   // group-private [chan][pt]
    float* msTb = sm + OFF_MS;               // msT[s] = msTb + s*2304, [pt][chan] stride MSP
    float* msTs = msTb + s * 2304;
    float* attv = sm + OFF_ATT;              // [pt][4]

    // ---- load weight A-fragments (tf32) once ----
    uint a1f[8][4], a2f[8][4];
#pragma unroll
    for (int kt = 0; kt < 8; kt++) {
        int kb = 8 * kt;
        a1f[kt][0] = f2tf(W1g[s * 4096 + (kb + tg) * 64 + m0]);
        a1f[kt][1] = f2tf(W1g[s * 4096 + (kb + tg) * 64 + m0 + 8]);
        a1f[kt][2] = f2tf(W1g[s * 4096 + (kb + tg + 4) * 64 + m0]);
        a1f[kt][3] = f2tf(W1g[s * 4096 + (kb + tg + 4) * 64 + m0 + 8]);
        a2f[kt][0] = f2tf(W2g[s * 4096 + (kb + tg) * 64 + m0]);
        a2f[kt][1] = f2tf(W2g[s * 4096 + (kb + tg) * 64 + m0 + 8]);
        a2f[kt][2] = f2tf(W2g[s * 4096 + (kb + tg + 4) * 64 + m0]);
        a2f[kt][3] = f2tf(W2g[s * 4096 + (kb + tg + 4) * 64 + m0 + 8]);
    }
    const float b1lo = b1g[s * 64 + m0], b1hi = b1g[s * 64 + m0 + 8];
    const float b2lo = b2g[s * 64 + m0], b2hi = b2g[s * 64 + m0 + 8];

    const int tiles = (n + 31) >> 5;

    for (int t = blockIdx.x; t < tiles; t += gridDim.x) {
        const int i0 = t * 32;

        // ---- phase 0: gather + transpose (each group for its own scale) ----
        {
            int p = l;                     // point in tile
            int i = i0 + p; if (i >= n) i = n - 1;
            int idx = g_ptidx[s][i];
            float inv = g_inv[s][idx];
            const float4* fr = (const float4*)&feats[(size_t)i * 64 + w * 16];
            const float4* sr = (const float4*)&g_sums[s][(size_t)idx * 64 + w * 16];
#pragma unroll
            for (int q = 0; q < 4; q++) {
                float4 f = fr[q];
                float4 sv = sr[q];
                int c = w * 16 + q * 4;
                if (s == 0) {
                    fT[(c + 0) * SP + p] = f.x;
                    fT[(c + 1) * SP + p] = f.y;
                    fT[(c + 2) * SP + p] = f.z;
                    fT[(c + 3) * SP + p] = f.w;
                }
                resT[(c + 0) * SP + p] = f.x - sv.x * inv;
                resT[(c + 1) * SP + p] = f.y - sv.y * inv;
                resT[(c + 2) * SP + p] = f.z - sv.z * inv;
                resT[(c + 3) * SP + p] = f.w - sv.w * inv;
            }
        }
        __syncthreads();

        // ---- phase 1: layer-1 MMAs, accumulators kept in registers ----
        float4 C[4];
#pragma unroll
        for (int nt = 0; nt < 4; nt++) {
            C[nt] = make_float4(0.f, 0.f, 0.f, 0.f);
            const int col = gr + nt * 8;
#pragma unroll
            for (int kt = 0; kt < 8; kt++) {
                uint b0 = f2tf(resT[(tg + kt * 8) * SP + col]);
                uint b1 = f2tf(resT[(tg + 4 + kt * 8) * SP + col]);
                mma_tf32(C[nt], a1f[kt], b0, b1);
            }
        }
        __syncthreads();   // all reads of resT done

        // ---- phase 2: h = relu(C+b1)*feats, overwrite resT ----
#pragma unroll
        for (int nt = 0; nt < 4; nt++) {
            int pc = 2 * tg + nt * 8;
            float2 flo = *(const float2*)&fT[m0 * SP + pc];
            float2 fhi = *(const float2*)&fT[(m0 + 8) * SP + pc];
            float2 hlo, hhi;
            hlo.x = fmaxf(C[nt].x + b1lo, 0.f) * flo.x;
            hlo.y = fmaxf(C[nt].y + b1lo, 0.f) * flo.y;
            hhi.x = fmaxf(C[nt].z + b1hi, 0.f) * fhi.x;
            hhi.y = fmaxf(C[nt].w + b1hi, 0.f) * fhi.y;
            *(float2*)&resT[m0 * SP + pc] = hlo;
            *(float2*)&resT[(m0 + 8) * SP + pc] = hhi;
        }
        __syncthreads();

        // ---- phase 3: layer-2 MMAs -> msT[s] ([pt][chan], stride MSP) ----
#pragma unroll
        for (int nt = 0; nt < 4; nt++) {
            float4 C2 = make_float4(0.f, 0.f, 0.f, 0.f);
            const int col = gr + nt * 8;
#pragma unroll
            for (int kt = 0; kt < 8; kt++) {
                uint b0 = f2tf(resT[(tg + kt * 8) * SP + col]);
                uint b1 = f2tf(resT[(tg + 4 + kt * 8) * SP + col]);
                mma_tf32(C2, a2f[kt], b0, b1);
            }
            int pc = 2 * tg + nt * 8;
            msTs[pc * MSP + m0]           = fmaxf(C2.x + b2lo, 0.f);
            msTs[(pc + 1) * MSP + m0]     = fmaxf(C2.y + b2lo, 0.f);
            msTs[pc * MSP + m0 + 8]       = fmaxf(C2.z + b2hi, 0.f);
            msTs[(pc + 1) * MSP + m0 + 8] = fmaxf(C2.w + b2hi, 0.f);
        }
        __syncthreads();

        // ---- phase 4: attention logits (12 warps cover 32 points) ----
        {
            int W = tid >> 5;
#pragma unroll
            for (int rep = 0; rep < 3; rep++) {
                int p = W + rep * 12;
                if (p < 32) {
                    float s0 = msTb[p * MSP + l]           + msTb[2304 + p * MSP + l]
                             + msTb[4608 + p * MSP + l];
                    float s1 = msTb[p * MSP + l + 32]      + msTb[2304 + p * MSP + l + 32]
                             + msTb[4608 + p * MSP + l + 32];
                    float pa0 = s0 * Wag[l]        + s1 * Wag[l + 32];
                    float pa1 = s0 * Wag[64 + l]   + s1 * Wag[96 + l];
                    float pa2 = s0 * Wag[128 + l]  + s1 * Wag[160 + l];
#pragma unroll
                    for (int off = 16; off; off >>= 1) {
                        pa0 += __shfl_xor_sync(0xffffffffu, pa0, off);
                        pa1 += __shfl_xor_sync(0xffffffffu, pa1, off);
                        pa2 += __shfl_xor_sync(0xffffffffu, pa2, off);
                    }
                    if (l == 0) {
                        attv[p * 4 + 0] = 1.0f / (1.0f + expf(-(pa0 + bag[0])));
                        attv[p * 4 + 1] = 1.0f / (1.0f + expf(-(pa1 + bag[1])));
                        attv[p * 4 + 2] = 1.0f / (1.0f + expf(-(pa2 + bag[2])));
                    }
                }
            }
        }
        __syncthreads();

        // ---- phase 5: output blend ----
#pragma unroll
        for (int j = 0; j < 6; j++) {
            int idx = tid + j * 384;
            if (idx < 2048) {
                int p = idx >> 6, c = idx & 63;
                if (i0 + p < n) {
                    float o = msTb[p * MSP + c]          * attv[p * 4 + 0]
                            + msTb[2304 + p * MSP + c]   * attv[p * 4 + 1]
                            + msTb[4608 + p * MSP + c]   * attv[p * 4 + 2];
                    out[(size_t)(i0 + p) * 64 + c] = o;
                }
            }
        }
        __syncthreads();   // WAR: protect smem before next tile's gather
    }
}

// ---------------- host launcher ----------------
extern "C" void kernel_launch(void* const* d_in, const int* in_sizes, int n_in,
                              void* d_out, int out_size) {
    const float* feats = (const float*)d_in[0];
    const int*   coords = (const int*)d_in[1];
    const float* W1 = (const float*)d_in[2];
    const float* b1 = (const float*)d_in[3];
    const float* W2 = (const float*)d_in[4];
    const float* b2 = (const float*)d_in[5];
    const float* Wa = (const float*)d_in[6];
    const float* ba = (const float*)d_in[7];
    float* out = (float*)d_out;

    int n = in_sizes[1] / 4;   // coords is (N,4) int32
    if (n > NMAX) n = NMAX;

    k_clear<<<2048, 256>>>(n);
    dim3 gi((n + 255) / 256, 3);
    k_insert<<<gi, 256>>>(coords, n);
    k_post<<<2048, 256>>>();
    k_accum<<<(n * 16 + 255) / 256, 256>>>(feats, n);
    k_select<<<gi, 256>>>(coords, n);

    int sms = 148;
    cudaDeviceGetAttribute(&sms, cudaDevAttrMultiProcessorCount, 0);
    cudaFuncSetAttribute(k_mlp3, cudaFuncAttributeMaxDynamicSharedMemorySize, SMEM_MLP);
    k_mlp3<<<sms, 384, SMEM_MLP>>>(feats, W1, b1, W2, b2, Wa, ba, out, n);
}